// round 5
// baseline (speedup 1.0000x reference)
#include <cuda_runtime.h>
#include <cstdint>

#define BB   16
#define XS_  256
#define NN   500000
#define LATD 8
#define NKX  129   // XS/2 + 1

// ---- static scratch (no allocs allowed) ----
__device__ float g_img [BB * XS_ * XS_];
__device__ float g_tmp [BB * XS_ * XS_];
__device__ float g_fre [BB * XS_ * NKX];
__device__ float g_fim [BB * XS_ * NKX];
__device__ float g_h   [BB * LATD];
__device__ float g_pose[BB * 8];

// ============================================================
// 0) zero image + pose/MLP prep (merged; disjoint arrays, no sync needed)
// ============================================================
__global__ void k_zero_prep(const float* __restrict__ rows,
                            const float* __restrict__ shifts,
                            const float* __restrict__ latent,
                            const float* __restrict__ W0, const float* __restrict__ b0,
                            const float* __restrict__ W1, const float* __restrict__ b1,
                            const float* __restrict__ W2, const float* __restrict__ b2,
                            const float* __restrict__ W3, const float* __restrict__ b3) {
    int i = blockIdx.x * blockDim.x + threadIdx.x;
    if (i < BB * XS_ * XS_) g_img[i] = 0.0f;

    if (blockIdx.x == 0 && threadIdx.x < BB) {
        int b = threadIdx.x;
        float rot = rows[b*3+0], tilt = rows[b*3+1], psi = rows[b*3+2];
        float ca = cosf(rot),  sa = sinf(rot);
        float cb = cosf(tilt), sb = sinf(tilt);
        float cg = cosf(psi),  sg = sinf(psi);

        float cgcb  = __fmul_rn(cg, cb);
        float nsgcb = __fmul_rn(-sg, cb);

        float r00 = __fsub_rn(__fmul_rn(cgcb, ca), __fmul_rn(sg, sa));
        float r01 = __fadd_rn(__fmul_rn(cgcb, sa), __fmul_rn(sg, ca));
        float r02 = -__fmul_rn(cg, sb);
        float r10 = __fsub_rn(__fmul_rn(nsgcb, ca), __fmul_rn(cg, sa));
        float r11 = __fadd_rn(__fmul_rn(nsgcb, sa), __fmul_rn(cg, ca));
        float r12 = __fmul_rn(sg, sb);

        g_pose[b*8+0] = r00;
        g_pose[b*8+1] = r01;
        g_pose[b*8+2] = r02;
        g_pose[b*8+3] = r10;
        g_pose[b*8+4] = r11;
        g_pose[b*8+5] = r12;
        g_pose[b*8+6] = shifts[b*2+0];
        g_pose[b*8+7] = shifts[b*2+1];

        float lat[LATD];
        #pragma unroll
        for (int ii = 0; ii < LATD; ii++) lat[ii] = latent[b*LATD+ii];

        float h[LATD], z[LATD];
        #pragma unroll
        for (int j = 0; j < LATD; j++) {
            float acc = 0.0f;
            #pragma unroll
            for (int ii = 0; ii < LATD; ii++) acc = fmaf(lat[ii], W0[ii*LATD+j], acc);
            acc = __fadd_rn(acc, b0[j]);
            h[j] = sinf(__fmul_rn(30.0f, acc));
        }
        const float* Ws[3] = {W1, W2, W3};
        const float* bs[3] = {b1, b2, b3};
        for (int L = 0; L < 3; L++) {
            #pragma unroll
            for (int j = 0; j < LATD; j++) {
                float acc = 0.0f;
                #pragma unroll
                for (int ii = 0; ii < LATD; ii++) acc = fmaf(h[ii], Ws[L][ii*LATD+j], acc);
                acc = __fadd_rn(acc, bs[L][j]);
                z[j] = sinf(acc);
            }
            #pragma unroll
            for (int j = 0; j < LATD; j++) h[j] = __fadd_rn(h[j], z[j]);
        }
        #pragma unroll
        for (int j = 0; j < LATD; j++) g_h[b*LATD+j] = h[j];
    }
}

// ============================================================
// 1) rotation + decode + scatter-add (thread per point, loop over B)
//    Arithmetic bit-identical to the 96.3us passing kernel.
// ============================================================
__global__ void __launch_bounds__(256)
k_scatter(const float* __restrict__ coords,
          const float* __restrict__ values,
          const float* __restrict__ Wd,
          const float* __restrict__ bd) {
    __shared__ float4 sh[BB * 2];   // h packed
    __shared__ float4 sp[BB * 2];   // pose packed
    int t = threadIdx.x;
    if (t < BB * 2) {
        const float4* gh = (const float4*)g_h;
        const float4* gp = (const float4*)g_pose;
        sh[t] = gh[t];
        sp[t] = gp[t];
    }
    __syncthreads();

    int n = blockIdx.x * blockDim.x + t;
    if (n >= NN) return;

    float x  = coords[3*n+0];
    float y  = coords[3*n+1];
    float zc = coords[3*n+2];
    float w[LATD];
    #pragma unroll
    for (int l = 0; l < LATD; l++) w[l] = Wd[l*NN + n];
    float vn  = values[n];
    float bdn = bd[n];

    #pragma unroll
    for (int b = 0; b < BB; b++) {
        float4 pa = sp[b*2+0];     // r00 r01 r02 r10
        float4 pb = sp[b*2+1];     // r11 r12 sx  sy
        float dx = fmaf(pa.x, x, 0.0f);
        dx = fmaf(pa.y, y,  dx);
        dx = fmaf(pa.z, zc, dx);
        float dy = fmaf(pa.w, x, 0.0f);
        dy = fmaf(pb.x, y,  dy);
        dy = fmaf(pb.y, zc, dy);
        float pxf = rintf(__fadd_rn(__fadd_rn(dx, pb.z), 128.0f));
        float pyf = rintf(__fadd_rn(__fadd_rn(dy, pb.w), 128.0f));
        pxf = fminf(fmaxf(pxf, 0.0f), 255.0f);
        pyf = fminf(fmaxf(pyf, 0.0f), 255.0f);
        int px = (int)pxf;
        int py = (int)pyf;

        float4 h0 = sh[b*2+0];
        float4 h1 = sh[b*2+1];
        float acc = 0.0f;
        acc = fmaf(h0.x, w[0], acc);
        acc = fmaf(h0.y, w[1], acc);
        acc = fmaf(h0.z, w[2], acc);
        acc = fmaf(h0.w, w[3], acc);
        acc = fmaf(h1.x, w[4], acc);
        acc = fmaf(h1.y, w[5], acc);
        acc = fmaf(h1.z, w[6], acc);
        acc = fmaf(h1.w, w[7], acc);
        float v = __fadd_rn(vn, __fadd_rn(acc, bdn));
        atomicAdd(&g_img[(b << 16) + (py << 8) + px], v);
    }
}

// ============================================================
// 2) separable Gaussian blur (sigma=1, radius=3, zero-padded SAME)
//    Identical arithmetic to the passing 96.3us kernel.
// ============================================================
__device__ __forceinline__ float gwt(int d) {
    const float w0 = 0.00443305f;   // |d|=3
    const float w1 = 0.05400558f;   // |d|=2
    const float w2 = 0.24203623f;   // |d|=1
    const float w3 = 0.39905033f;   // d=0
    int a = d < 0 ? -d : d;
    return a == 0 ? w3 : (a == 1 ? w2 : (a == 2 ? w1 : w0));
}

__global__ void k_blur_v() {   // along y (H), g_img -> g_tmp
    int i = blockIdx.x * blockDim.x + threadIdx.x;
    if (i >= BB * XS_ * XS_) return;
    int x = i & 255;
    int y = (i >> 8) & 255;
    int b = i >> 16;
    float acc = 0.0f;
    #pragma unroll
    for (int d = -3; d <= 3; d++) {
        int yy = y + d;
        if (yy >= 0 && yy < XS_)
            acc += gwt(d) * g_img[(b*XS_ + yy)*XS_ + x];
    }
    g_tmp[i] = acc;
}

__global__ void k_blur_h() {   // along x (W), g_tmp -> g_img
    int i = blockIdx.x * blockDim.x + threadIdx.x;
    if (i >= BB * XS_ * XS_) return;
    int x = i & 255;
    float acc = 0.0f;
    #pragma unroll
    for (int d = -3; d <= 3; d++) {
        int xx = x + d;
        if (xx >= 0 && xx < XS_)
            acc += gwt(d) * g_tmp[i - x + xx];
    }
    g_img[i] = acc;
}

// ============================================================
// 256-point radix-2 DIT FFT, shared twiddle table, 128 threads.
// ============================================================
__device__ __forceinline__ void fft256_tw(float* sre, float* sim,
                                          const float2* tw, int t, bool inv) {
    #pragma unroll
    for (int s = 1; s <= 8; s++) {
        int len  = 1 << s;
        int half = len >> 1;
        int grp = t >> (s - 1);
        int j   = t & (half - 1);
        int i0  = grp * len + j;
        int i1  = i0 + half;
        float2 w = tw[j << (8 - s)];
        float wr = w.x;
        float wi = inv ? -w.y : w.y;
        float xr = sre[i1], xi = sim[i1];
        float vr = xr*wr - xi*wi;
        float vi = xr*wi + xi*wr;
        float ur = sre[i0], ui = sim[i0];
        sre[i0] = ur + vr;  sim[i0] = ui + vi;
        sre[i1] = ur - vr;  sim[i1] = ui - vi;
        __syncthreads();
    }
}

__device__ __forceinline__ int brev8(int i) { return (int)(__brev((unsigned)i) >> 24); }

__device__ __forceinline__ void init_tw(float2* tw, int t) {
    float s, c;
    sincospif((float)t * (1.0f / 128.0f), &s, &c);
    tw[t] = make_float2(c, -s);
}

// 3) row-wise rfft: g_img rows -> g_fre/g_fim [row][0..128]
__global__ void __launch_bounds__(128) k_rfft_row() {
    __shared__ float sre[256], sim[256];
    __shared__ float2 tw[128];
    int t = threadIdx.x;
    init_tw(tw, t);
    int row = blockIdx.x;                 // b*256 + y
    const float* src = &g_img[row * XS_];
    sre[t]       = src[brev8(t)];        sim[t]       = 0.0f;
    sre[t + 128] = src[brev8(t + 128)];  sim[t + 128] = 0.0f;
    __syncthreads();
    fft256_tw(sre, sim, tw, t, false);
    float* dre = &g_fre[row * NKX];
    float* dim = &g_fim[row * NKX];
    dre[t] = sre[t];  dim[t] = sim[t];
    if (t == 0) { dre[128] = sre[128]; dim[128] = sim[128]; }
}

// 4) column FFT over y, multiply by CTF, inverse column FFT (fused)
__global__ void __launch_bounds__(128) k_col_ctf(const float* __restrict__ ctf) {
    __shared__ float sre[256], sim[256];
    __shared__ float2 tw[128];
    int t  = threadIdx.x;
    init_tw(tw, t);
    int b  = blockIdx.x / NKX;
    int kx = blockIdx.x % NKX;
    int base = b * XS_ * NKX + kx;

    int r0 = brev8(t), r1 = brev8(t + 128);
    sre[t]       = g_fre[base + r0 * NKX];  sim[t]       = g_fim[base + r0 * NKX];
    sre[t + 128] = g_fre[base + r1 * NKX];  sim[t + 128] = g_fim[base + r1 * NKX];
    __syncthreads();
    fft256_tw(sre, sim, tw, t, false);

    const float* cp = &ctf[base];
    float c0 = cp[t * NKX];
    float c1 = cp[(t + 128) * NKX];
    float ar = sre[t]       * c0, ai = sim[t]       * c0;
    float br = sre[t + 128] * c1, bi = sim[t + 128] * c1;
    __syncthreads();
    sre[r0] = ar;  sim[r0] = ai;
    sre[r1] = br;  sim[r1] = bi;
    __syncthreads();
    fft256_tw(sre, sim, tw, t, true);     // unscaled inverse

    g_fre[base + t * NKX]         = sre[t];
    g_fim[base + t * NKX]         = sim[t];
    g_fre[base + (t + 128) * NKX] = sre[t + 128];
    g_fim[base + (t + 128) * NKX] = sim[t + 128];
}

// 5) row-wise inverse rfft (Hermitian reconstruct) -> d_out, scale 1/65536
__global__ void __launch_bounds__(128) k_irfft_row(float* __restrict__ out) {
    __shared__ float sre[256], sim[256];
    __shared__ float2 tw[128];
    int t = threadIdx.x;
    init_tw(tw, t);
    int row = blockIdx.x;                 // b*256 + y
    const float* dre = &g_fre[row * NKX];
    const float* dim = &g_fim[row * NKX];
    #pragma unroll
    for (int i = t; i < 256; i += 128) {
        int k = brev8(i);
        float re, im;
        if (k <= 128) { re = dre[k];        im =  dim[k]; }
        else          { re = dre[256 - k];  im = -dim[256 - k]; }
        sre[i] = re;  sim[i] = im;
    }
    __syncthreads();
    fft256_tw(sre, sim, tw, t, true);
    const float s = 1.0f / 65536.0f;      // 1/(256*256)
    out[row * XS_ + t]       = sre[t]       * s;
    out[row * XS_ + t + 128] = sre[t + 128] * s;
}

// ============================================================
extern "C" void kernel_launch(void* const* d_in, const int* in_sizes, int n_in,
                              void* d_out, int out_size) {
    const float* rows   = (const float*)d_in[0];
    const float* shifts = (const float*)d_in[1];
    const float* latent = (const float*)d_in[2];
    const float* coords = (const float*)d_in[3];
    const float* values = (const float*)d_in[4];
    const float* W0     = (const float*)d_in[5];
    const float* b0     = (const float*)d_in[6];
    const float* W1     = (const float*)d_in[7];
    const float* b1     = (const float*)d_in[8];
    const float* W2     = (const float*)d_in[9];
    const float* b2     = (const float*)d_in[10];
    const float* W3     = (const float*)d_in[11];
    const float* b3     = (const float*)d_in[12];
    const float* Wd     = (const float*)d_in[13];
    const float* bd     = (const float*)d_in[14];
    const float* ctf    = (const float*)d_in[15];
    float* out = (float*)d_out;

    const int IMG = BB * XS_ * XS_;
    k_zero_prep<<<(IMG + 255) / 256, 256>>>(rows, shifts, latent,
                                            W0, b0, W1, b1, W2, b2, W3, b3);
    k_scatter<<<(NN + 255) / 256, 256>>>(coords, values, Wd, bd);
    k_blur_v<<<(IMG + 255) / 256, 256>>>();
    k_blur_h<<<(IMG + 255) / 256, 256>>>();
    k_rfft_row<<<BB * XS_, 128>>>();
    k_col_ctf<<<BB * NKX, 128>>>(ctf);
    k_irfft_row<<<BB * XS_, 128>>>(out);
}